// round 15
// baseline (speedup 1.0000x reference)
#include <cuda_runtime.h>
#include <math_constants.h>

// MAM dense: C[n,j] = max_k(x[n,k]*w[j,k]) + min_k(x[n,k]*w[j,k]) + bias[j]
// x: [2048, 512] f32, w: [256, 512] f32, bias: [256] f32, out: [2048, 256] f32
//
// R15: 2n x 4j thread tile (0.75 loaded-floats/product) with the k2-paired
// TREE reduction from R9/R12. R11/R14 (same tile, serial acc = fmax(acc,p)
// chains) showed effective FMNMX rt~2 (alu=60% @ 103K cyc) vs R12's tree
// pattern rt~1 (alu=41%): serial accumulator chains hit RF-bank/rt penalties.
// Inner k2 (2 k's): 3x LDS.128 -> 16 FMUL + 16 pair-minmax + 16 acc-minmax.
// Tile 32n x 32j, 512 CTAs, 128 thr, double-buffered smem, 1 barrier/chunk.

constexpr int IN_F  = 512;
constexpr int OUT_F = 256;
constexpr int NROWS = 2048;

constexpr int TN = 32;
constexpr int TJ = 32;
constexpr int KB = 32;
constexpr int NCH = IN_F / KB;                   // 16
constexpr int TILES_J = OUT_F / TJ;              // 8
constexpr int NTILES  = (NROWS / TN) * TILES_J;  // 512
constexpr int THREADS = 128;

constexpr int XLD2 = 68;   // floats per k2-row of xs2: 32n*2 + pad = 17*16B
constexpr int WLD2 = 68;   // floats per k2-row of ws2: 32j*2 + pad = 17*16B

__global__ __launch_bounds__(THREADS, 4)
void mam_kernel(const float* __restrict__ x,
                const float* __restrict__ w,
                const float* __restrict__ bias,
                float* __restrict__ out)
{
    // Double-buffered k-pair-packed tiles: t[k2][row][2] (k parity innermost).
    __shared__ __align__(16) float xs2[2][(KB / 2) * XLD2];
    __shared__ __align__(16) float ws2[2][(KB / 2) * WLD2];

    const int tid = threadIdx.x;
    const int tn  = tid >> 3;          // 0..15 -> n pair   (n = n0 + 2*tn)
    const int tj  = tid & 7;           // 0..7  -> j quad   (j = j0 + 4*tj)
    const int j0  = (blockIdx.x & (TILES_J - 1)) * TJ;
    const int n0  = (blockIdx.x / TILES_J) * TN;

    // Loader mapping (coalesced: 4 consecutive rows per warp quarter).
    const int lr  = tid >> 3;          // 0..15 (rows lr, lr+16)
    const int lkq = (tid & 7) * 4;     // k quad: 0,4,...,28
    const int lk2 = lkq >> 1;          // k2 base

    const float* xb = &x[(n0 + lr) * IN_F + lkq];
    const float* wb = &w[(j0 + lr) * IN_F + lkq];

    float mx[2][4], mn[2][4];
#pragma unroll
    for (int i = 0; i < 2; i++)
#pragma unroll
        for (int jj = 0; jj < 4; jj++) {
            mx[i][jj] = -CUDART_INF_F;
            mn[i][jj] =  CUDART_INF_F;
        }

    // Prefetch chunk 0.
    float4 xv0 = *reinterpret_cast<const float4*>(xb);
    float4 xv1 = *reinterpret_cast<const float4*>(xb + 16 * IN_F);
    float4 wv0 = *reinterpret_cast<const float4*>(wb);
    float4 wv1 = *reinterpret_cast<const float4*>(wb + 16 * IN_F);

    // k2-pack staging: float4 (4 k at row r) -> 2x STS.64 into rows lk2, lk2+1.
#define STAGE(BUF)                                                            \
    {                                                                         \
        float* xa = xs2[BUF] + lk2 * XLD2 + 2 * lr;                           \
        *reinterpret_cast<float2*>(xa)         = make_float2(xv0.x, xv0.y);   \
        *reinterpret_cast<float2*>(xa + XLD2)  = make_float2(xv0.z, xv0.w);   \
        float* xc = xs2[BUF] + lk2 * XLD2 + 2 * (lr + 16);                    \
        *reinterpret_cast<float2*>(xc)         = make_float2(xv1.x, xv1.y);   \
        *reinterpret_cast<float2*>(xc + XLD2)  = make_float2(xv1.z, xv1.w);   \
        float* wa = ws2[BUF] + lk2 * WLD2 + 2 * lr;                           \
        *reinterpret_cast<float2*>(wa)         = make_float2(wv0.x, wv0.y);   \
        *reinterpret_cast<float2*>(wa + WLD2)  = make_float2(wv0.z, wv0.w);   \
        float* wc = ws2[BUF] + lk2 * WLD2 + 2 * (lr + 16);                    \
        *reinterpret_cast<float2*>(wc)         = make_float2(wv1.x, wv1.y);   \
        *reinterpret_cast<float2*>(wc + WLD2)  = make_float2(wv1.z, wv1.w);   \
    }

    STAGE(0)
    __syncthreads();   // buffer 0 ready

    for (int c = 0; c < NCH; c++) {
        // LDG next chunk first (latency overlapped with compute).
        const bool more = (c + 1) < NCH;
        if (more) {
            const int kn = (c + 1) * KB;
            xv0 = *reinterpret_cast<const float4*>(xb + kn);
            xv1 = *reinterpret_cast<const float4*>(xb + 16 * IN_F + kn);
            wv0 = *reinterpret_cast<const float4*>(wb + kn);
            wv1 = *reinterpret_cast<const float4*>(wb + 16 * IN_F + kn);
        }

        const int cb = c & 1;
        const float* agp = xs2[cb] + 4 * tn;   // {x[k0,n0],x[k1,n0],x[k0,n1],x[k1,n1]}
        const float* bgp = ws2[cb] + 8 * tj;   // j quad, k-pair packed

#pragma unroll
        for (int k2 = 0; k2 < KB / 2; k2++) {
            const float4 a  = *reinterpret_cast<const float4*>(agp + k2 * XLD2);
            const float4 b0 = *reinterpret_cast<const float4*>(bgp + k2 * WLD2);
            const float4 b1 = *reinterpret_cast<const float4*>(bgp + k2 * WLD2 + 4);

            // n-row 0 (a.x = k0, a.y = k1)
            {
                const float pj0k0 = a.x * b0.x, pj0k1 = a.y * b0.y;
                const float pj1k0 = a.x * b0.z, pj1k1 = a.y * b0.w;
                const float pj2k0 = a.x * b1.x, pj2k1 = a.y * b1.y;
                const float pj3k0 = a.x * b1.z, pj3k1 = a.y * b1.w;
                mx[0][0] = fmaxf(mx[0][0], fmaxf(pj0k0, pj0k1));
                mn[0][0] = fminf(mn[0][0], fminf(pj0k0, pj0k1));
                mx[0][1] = fmaxf(mx[0][1], fmaxf(pj1k0, pj1k1));
                mn[0][1] = fminf(mn[0][1], fminf(pj1k0, pj1k1));
                mx[0][2] = fmaxf(mx[0][2], fmaxf(pj2k0, pj2k1));
                mn[0][2] = fminf(mn[0][2], fminf(pj2k0, pj2k1));
                mx[0][3] = fmaxf(mx[0][3], fmaxf(pj3k0, pj3k1));
                mn[0][3] = fminf(mn[0][3], fminf(pj3k0, pj3k1));
            }
            // n-row 1 (a.z = k0, a.w = k1)
            {
                const float pj0k0 = a.z * b0.x, pj0k1 = a.w * b0.y;
                const float pj1k0 = a.z * b0.z, pj1k1 = a.w * b0.w;
                const float pj2k0 = a.z * b1.x, pj2k1 = a.w * b1.y;
                const float pj3k0 = a.z * b1.z, pj3k1 = a.w * b1.w;
                mx[1][0] = fmaxf(mx[1][0], fmaxf(pj0k0, pj0k1));
                mn[1][0] = fminf(mn[1][0], fminf(pj0k0, pj0k1));
                mx[1][1] = fmaxf(mx[1][1], fmaxf(pj1k0, pj1k1));
                mn[1][1] = fminf(mn[1][1], fminf(pj1k0, pj1k1));
                mx[1][2] = fmaxf(mx[1][2], fmaxf(pj2k0, pj2k1));
                mn[1][2] = fminf(mn[1][2], fminf(pj2k0, pj2k1));
                mx[1][3] = fmaxf(mx[1][3], fmaxf(pj3k0, pj3k1));
                mn[1][3] = fminf(mn[1][3], fminf(pj3k0, pj3k1));
            }
        }

        // Stage next chunk into the other buffer; single barrier gives both
        // orderings (buffer fully consumed above; stores visible next iter).
        if (more) {
            const int nb = (c + 1) & 1;
            if (nb) { STAGE(1) } else { STAGE(0) }
            __syncthreads();
        }
    }
#undef STAGE

    // Epilogue: C = max + min + bias (two STG.128).
    const int j = j0 + 4 * tj;
    const int n = n0 + 2 * tn;
    const float4 bz = *reinterpret_cast<const float4*>(&bias[j]);
#pragma unroll
    for (int i = 0; i < 2; i++) {
        float4 r;
        r.x = mx[i][0] + mn[i][0] + bz.x;
        r.y = mx[i][1] + mn[i][1] + bz.y;
        r.z = mx[i][2] + mn[i][2] + bz.z;
        r.w = mx[i][3] + mn[i][3] + bz.w;
        *reinterpret_cast<float4*>(&out[(n + i) * OUT_F + j]) = r;
    }
}

extern "C" void kernel_launch(void* const* d_in, const int* in_sizes, int n_in,
                              void* d_out, int out_size)
{
    const float* x    = (const float*)d_in[0];   // [2048, 512]
    const float* w    = (const float*)d_in[1];   // [256, 512]
    const float* bias = (const float*)d_in[2];   // [256]
    float* out        = (float*)d_out;           // [2048, 256]

    mam_kernel<<<NTILES, THREADS>>>(x, w, bias, out);
}

// round 16
// speedup vs baseline: 1.1481x; 1.1481x over previous
#include <cuda_runtime.h>
#include <math_constants.h>

// MAM dense: C[n,j] = max_k(x[n,k]*w[j,k]) + min_k(x[n,k]*w[j,k]) + bias[j]
// x: [2048, 512] f32, w: [256, 512] f32, bias: [256] f32, out: [2048, 256] f32
//
// R16: R12's inner math (k2-paired tree, rt=1 verified) with the b-operand
// made WARP-UNIFORM: warp owns a j-pair, so the b LDS.128 is a broadcast
// (~1 wavefront vs 4). Inner l1tex wf drops 8 -> 5 per warp-k2.
// Tile 64n x 8j, 128 thr, 1024 CTAs: same 6.92 warps/SMSP + 7v6 balance as
// R12. Double-buffered smem, one __syncthreads per k-chunk.

constexpr int IN_F  = 512;
constexpr int OUT_F = 256;
constexpr int NROWS = 2048;

constexpr int TN = 64;
constexpr int TJ = 8;
constexpr int KB = 32;
constexpr int NCH = IN_F / KB;                   // 16
constexpr int TILES_J = OUT_F / TJ;              // 32
constexpr int NTILES  = (NROWS / TN) * TILES_J;  // 1024
constexpr int THREADS = 128;

constexpr int XLD2 = 132;  // floats per k2-row of xs2: 64n*2 + 4 pad (16B-aligned)
constexpr int WLD2 = 20;   // floats per k2-row of ws2:  8j*2 + 4 pad (16B-aligned)

__global__ __launch_bounds__(THREADS, 7)
void mam_kernel(const float* __restrict__ x,
                const float* __restrict__ w,
                const float* __restrict__ bias,
                float* __restrict__ out)
{
    // Double-buffered k-pair-packed tiles: t[k2][row][2] (k parity innermost).
    __shared__ __align__(16) float xs2[2][(KB / 2) * XLD2];
    __shared__ __align__(16) float ws2[2][(KB / 2) * WLD2];

    const int tid  = threadIdx.x;
    const int lane = tid & 31;
    const int wid  = tid >> 5;
    const int j0   = (blockIdx.x & (TILES_J - 1)) * TJ;
    const int n0   = (blockIdx.x / TILES_J) * TN;

    // x loader: 64 rows x 32 k = 512 float4; thread owns rows lr+16*r4 (r4=0..3)
    // at k-quad lkq.
    const int lr  = tid >> 3;          // 0..15
    const int lkq = (tid & 7) * 4;     // 0,4,...,28
    const int lk2 = lkq >> 1;

    // w loader: 8 rows x 32 k = 64 float4; threads 0..63 own one each.
    const bool wload = tid < 64;
    const int  wj    = tid >> 3;       // 0..7 (only used when wload)
    const int  wkq   = (tid & 7) * 4;
    const int  wk2   = wkq >> 1;

    const float* xb = &x[(n0 + lr) * IN_F + lkq];
    const float* wb = &w[(j0 + wj) * IN_F + wkq];

    float mx[2][2], mn[2][2];
#pragma unroll
    for (int i = 0; i < 2; i++)
#pragma unroll
        for (int jj = 0; jj < 2; jj++) {
            mx[i][jj] = -CUDART_INF_F;
            mn[i][jj] =  CUDART_INF_F;
        }

    // Prefetch chunk 0.
    float4 xv[4];
#pragma unroll
    for (int r4 = 0; r4 < 4; r4++)
        xv[r4] = *reinterpret_cast<const float4*>(xb + r4 * 16 * IN_F);
    float4 wv;
    if (wload) wv = *reinterpret_cast<const float4*>(wb);

    // k2-pack staging: float4 (4 consecutive k at one row) -> 2x STS.64.
#define STAGE(BUF)                                                            \
    {                                                                         \
        _Pragma("unroll")                                                     \
        for (int r4 = 0; r4 < 4; r4++) {                                      \
            float* xa = xs2[BUF] + lk2 * XLD2 + 2 * (lr + 16 * r4);           \
            *reinterpret_cast<float2*>(xa)        = make_float2(xv[r4].x, xv[r4].y); \
            *reinterpret_cast<float2*>(xa + XLD2) = make_float2(xv[r4].z, xv[r4].w); \
        }                                                                     \
        if (wload) {                                                          \
            float* wa = ws2[BUF] + wk2 * WLD2 + 2 * wj;                       \
            *reinterpret_cast<float2*>(wa)        = make_float2(wv.x, wv.y);  \
            *reinterpret_cast<float2*>(wa + WLD2) = make_float2(wv.z, wv.w);  \
        }                                                                     \
    }

    STAGE(0)
    __syncthreads();   // buffer 0 ready

    const int aoff = 4 * lane;   // n-pair 2*lane: [k2][2*lane][0..1],[2*lane+1][0..1]
    const int boff = 4 * wid;    // j-pair 2*wid (warp-uniform)

    for (int c = 0; c < NCH; c++) {
        // LDG next chunk first (latency overlapped with compute).
        const bool more = (c + 1) < NCH;
        if (more) {
            const int kn = (c + 1) * KB;
#pragma unroll
            for (int r4 = 0; r4 < 4; r4++)
                xv[r4] = *reinterpret_cast<const float4*>(xb + r4 * 16 * IN_F + kn);
            if (wload) wv = *reinterpret_cast<const float4*>(wb + kn);
        }

        const int cb = c & 1;
        const float* agp = xs2[cb] + aoff;
        const float* bgp = ws2[cb] + boff;

#pragma unroll
        for (int k2 = 0; k2 < KB / 2; k2++) {
            // a = {x[k0,n0], x[k1,n0], x[k0,n1], x[k1,n1]}   (per-lane)
            // b = {w[k0,j0], w[k1,j0], w[k0,j1], w[k1,j1]}   (warp-uniform)
            const float4 a = *reinterpret_cast<const float4*>(agp + k2 * XLD2);
            const float4 b = *reinterpret_cast<const float4*>(bgp + k2 * WLD2);

            const float p000 = a.x * b.x;   // (n0,j0,k0)
            const float p001 = a.y * b.y;   // (n0,j0,k1)
            const float p010 = a.x * b.z;   // (n0,j1,k0)
            const float p011 = a.y * b.w;   // (n0,j1,k1)
            const float p100 = a.z * b.x;   // (n1,j0,k0)
            const float p101 = a.w * b.y;   // (n1,j0,k1)
            const float p110 = a.z * b.z;   // (n1,j1,k0)
            const float p111 = a.w * b.w;   // (n1,j1,k1)

            mx[0][0] = fmaxf(mx[0][0], fmaxf(p000, p001));
            mn[0][0] = fminf(mn[0][0], fminf(p000, p001));
            mx[0][1] = fmaxf(mx[0][1], fmaxf(p010, p011));
            mn[0][1] = fminf(mn[0][1], fminf(p010, p011));
            mx[1][0] = fmaxf(mx[1][0], fmaxf(p100, p101));
            mn[1][0] = fminf(mn[1][0], fminf(p100, p101));
            mx[1][1] = fmaxf(mx[1][1], fmaxf(p110, p111));
            mn[1][1] = fminf(mn[1][1], fminf(p110, p111));
        }

        // Stage next chunk into the other buffer; single barrier provides
        // both orderings (buffer consumed above; stores visible next iter).
        if (more) {
            const int nb = (c + 1) & 1;
            if (nb) { STAGE(1) } else { STAGE(0) }
            __syncthreads();
        }
    }
#undef STAGE

    // Epilogue: C = max + min + bias (two STG.64 per thread).
    const int n = n0 + 2 * lane;
    const int j = j0 + 2 * wid;
    const float b0 = bias[j];
    const float b1 = bias[j + 1];
#pragma unroll
    for (int i = 0; i < 2; i++) {
        float2 r;
        r.x = mx[i][0] + mn[i][0] + b0;
        r.y = mx[i][1] + mn[i][1] + b1;
        *reinterpret_cast<float2*>(&out[(n + i) * OUT_F + j]) = r;
    }
}

extern "C" void kernel_launch(void* const* d_in, const int* in_sizes, int n_in,
                              void* d_out, int out_size)
{
    const float* x    = (const float*)d_in[0];   // [2048, 512]
    const float* w    = (const float*)d_in[1];   // [256, 512]
    const float* bias = (const float*)d_in[2];   // [256]
    float* out        = (float*)d_out;           // [2048, 256]

    mam_kernel<<<NTILES, THREADS>>>(x, w, bias, out);
}

// round 17
// speedup vs baseline: 1.4308x; 1.2462x over previous
#include <cuda_runtime.h>
#include <math_constants.h>

// MAM dense: C[n,j] = max_k(x[n,k]*w[j,k]) + min_k(x[n,k]*w[j,k]) + bias[j]
// x: [2048, 512] f32, w: [256, 512] f32, bias: [256] f32, out: [2048, 256] f32
//
// R17: 2n x 4j thread tile (L1 wf 43K/SM < issue floor 46K slots/SMSP) with
//  - R14's conflict-free strides (verified L1=52%): a LDS.64 @ 2*tn,
//    b LDS.128 @ 4*tj (banks 0,4,...,28),
//  - R12's k-pair tree reduction (verified rt=1, no serial-chain penalty),
//  - k-split 2 -> 1024 CTAs: 6.92 warps/SMSP + 7v6 balance (fixes the 512-CTA
//    3.46-warp / 4v3 weakness that sank R11/R14/R15),
//  - cheap combine kernel (8.4MB scratch, L2-resident).

constexpr int IN_F  = 512;
constexpr int OUT_F = 256;
constexpr int NROWS = 2048;

constexpr int TN = 32;
constexpr int TJ = 32;
constexpr int KB = 32;
constexpr int NSPLIT = 2;
constexpr int KSPL = IN_F / NSPLIT;              // 256
constexpr int NCH = KSPL / KB;                   // 8
constexpr int THREADS = 128;

constexpr int XLD = 34;  // xs[k][n] stride (even -> LDS.64 aligned; conflict-free)
constexpr int WLD = 36;  // ws[k][j] stride (mult of 4 -> LDS.128 aligned; conflict-free)

// Scratch partials: [split][n][j]
__device__ float g_pmax[NSPLIT * NROWS * OUT_F];
__device__ float g_pmin[NSPLIT * NROWS * OUT_F];

__global__ __launch_bounds__(THREADS, 7)
void mam_partial_kernel(const float* __restrict__ x,
                        const float* __restrict__ w)
{
    __shared__ __align__(16) float xs[2][KB][XLD];
    __shared__ __align__(16) float ws[2][KB][WLD];

    const int tid = threadIdx.x;
    const int tn  = tid >> 3;          // 0..15 -> n pair
    const int tj  = tid & 7;           // 0..7  -> j quad
    const int j0  = blockIdx.x * TJ;
    const int n0  = blockIdx.y * TN;
    const int ks  = blockIdx.z * KSPL;

    // Loader mapping (coalesced: 4 consecutive rows per warp quarter).
    const int lr  = tid >> 3;          // 0..15 (rows lr, lr+16)
    const int lkq = (tid & 7) * 4;     // k quad: 0,4,...,28

    const float* xb = &x[(n0 + lr) * IN_F + ks + lkq];
    const float* wb = &w[(j0 + lr) * IN_F + ks + lkq];

    float mx[2][4], mn[2][4];
#pragma unroll
    for (int i = 0; i < 2; i++)
#pragma unroll
        for (int jj = 0; jj < 4; jj++) {
            mx[i][jj] = -CUDART_INF_F;
            mn[i][jj] =  CUDART_INF_F;
        }

    // Prefetch chunk 0.
    float4 xv0 = *reinterpret_cast<const float4*>(xb);
    float4 xv1 = *reinterpret_cast<const float4*>(xb + 16 * IN_F);
    float4 wv0 = *reinterpret_cast<const float4*>(wb);
    float4 wv1 = *reinterpret_cast<const float4*>(wb + 16 * IN_F);

#define STAGE(BUF)                                                            \
    {                                                                         \
        xs[BUF][lkq + 0][lr]      = xv0.x; xs[BUF][lkq + 1][lr]      = xv0.y; \
        xs[BUF][lkq + 2][lr]      = xv0.z; xs[BUF][lkq + 3][lr]      = xv0.w; \
        xs[BUF][lkq + 0][lr + 16] = xv1.x; xs[BUF][lkq + 1][lr + 16] = xv1.y; \
        xs[BUF][lkq + 2][lr + 16] = xv1.z; xs[BUF][lkq + 3][lr + 16] = xv1.w; \
        ws[BUF][lkq + 0][lr]      = wv0.x; ws[BUF][lkq + 1][lr]      = wv0.y; \
        ws[BUF][lkq + 2][lr]      = wv0.z; ws[BUF][lkq + 3][lr]      = wv0.w; \
        ws[BUF][lkq + 0][lr + 16] = wv1.x; ws[BUF][lkq + 1][lr + 16] = wv1.y; \
        ws[BUF][lkq + 2][lr + 16] = wv1.z; ws[BUF][lkq + 3][lr + 16] = wv1.w; \
    }

    STAGE(0)
    __syncthreads();   // buffer 0 ready

    const float* agp0 = &xs[0][0][2 * tn];
    const float* bgp0 = &ws[0][0][4 * tj];
    const float* agp1 = &xs[1][0][2 * tn];
    const float* bgp1 = &ws[1][0][4 * tj];

    for (int c = 0; c < NCH; c++) {
        // LDG next chunk first (latency overlapped with compute).
        const bool more = (c + 1) < NCH;
        if (more) {
            const int kn = (c + 1) * KB;
            xv0 = *reinterpret_cast<const float4*>(xb + kn);
            xv1 = *reinterpret_cast<const float4*>(xb + 16 * IN_F + kn);
            wv0 = *reinterpret_cast<const float4*>(wb + kn);
            wv1 = *reinterpret_cast<const float4*>(wb + 16 * IN_F + kn);
        }

        const float* agp = (c & 1) ? agp1 : agp0;
        const float* bgp = (c & 1) ? bgp1 : bgp0;

        // k-pair tree: per k2, 4 LDS + 16 FMUL + 16 pair-minmax + 16 acc.
#pragma unroll
        for (int k2 = 0; k2 < KB / 2; k2++) {
            const float2 a0 = *reinterpret_cast<const float2*>(agp + (2 * k2) * XLD);
            const float2 a1 = *reinterpret_cast<const float2*>(agp + (2 * k2 + 1) * XLD);
            const float4 b0 = *reinterpret_cast<const float4*>(bgp + (2 * k2) * WLD);
            const float4 b1 = *reinterpret_cast<const float4*>(bgp + (2 * k2 + 1) * WLD);

            // n-row 0
            {
                const float q0 = a0.x * b0.x, r0 = a1.x * b1.x;
                const float q1 = a0.x * b0.y, r1 = a1.x * b1.y;
                const float q2 = a0.x * b0.z, r2 = a1.x * b1.z;
                const float q3 = a0.x * b0.w, r3 = a1.x * b1.w;
                mx[0][0] = fmaxf(mx[0][0], fmaxf(q0, r0));
                mn[0][0] = fminf(mn[0][0], fminf(q0, r0));
                mx[0][1] = fmaxf(mx[0][1], fmaxf(q1, r1));
                mn[0][1] = fminf(mn[0][1], fminf(q1, r1));
                mx[0][2] = fmaxf(mx[0][2], fmaxf(q2, r2));
                mn[0][2] = fminf(mn[0][2], fminf(q2, r2));
                mx[0][3] = fmaxf(mx[0][3], fmaxf(q3, r3));
                mn[0][3] = fminf(mn[0][3], fminf(q3, r3));
            }
            // n-row 1
            {
                const float q0 = a0.y * b0.x, r0 = a1.y * b1.x;
                const float q1 = a0.y * b0.y, r1 = a1.y * b1.y;
                const float q2 = a0.y * b0.z, r2 = a1.y * b1.z;
                const float q3 = a0.y * b0.w, r3 = a1.y * b1.w;
                mx[1][0] = fmaxf(mx[1][0], fmaxf(q0, r0));
                mn[1][0] = fminf(mn[1][0], fminf(q0, r0));
                mx[1][1] = fmaxf(mx[1][1], fmaxf(q1, r1));
                mn[1][1] = fminf(mn[1][1], fminf(q1, r1));
                mx[1][2] = fmaxf(mx[1][2], fmaxf(q2, r2));
                mn[1][2] = fminf(mn[1][2], fminf(q2, r2));
                mx[1][3] = fmaxf(mx[1][3], fmaxf(q3, r3));
                mn[1][3] = fminf(mn[1][3], fminf(q3, r3));
            }
        }

        // Stage next chunk into the other buffer; single barrier provides
        // both orderings (buffer consumed above; stores visible next iter).
        if (more) {
            if ((c + 1) & 1) { STAGE(1) } else { STAGE(0) }
            __syncthreads();
        }
    }
#undef STAGE

    // Write partials (two STG.128 per array).
    float* pmax = &g_pmax[blockIdx.z * (NROWS * OUT_F)];
    float* pmin = &g_pmin[blockIdx.z * (NROWS * OUT_F)];
    const int j = j0 + 4 * tj;
    const int n = n0 + 2 * tn;
#pragma unroll
    for (int i = 0; i < 2; i++) {
        *reinterpret_cast<float4*>(&pmax[(n + i) * OUT_F + j]) =
            make_float4(mx[i][0], mx[i][1], mx[i][2], mx[i][3]);
        *reinterpret_cast<float4*>(&pmin[(n + i) * OUT_F + j]) =
            make_float4(mn[i][0], mn[i][1], mn[i][2], mn[i][3]);
    }
}

__global__ __launch_bounds__(256)
void mam_combine_kernel(const float* __restrict__ bias,
                        float* __restrict__ out)
{
    const int v = blockIdx.x * blockDim.x + threadIdx.x;   // float4 index
    const float4 ma = reinterpret_cast<const float4*>(g_pmax)[v];
    const float4 mb = reinterpret_cast<const float4*>(g_pmax + NROWS * OUT_F)[v];
    const float4 na = reinterpret_cast<const float4*>(g_pmin)[v];
    const float4 nb = reinterpret_cast<const float4*>(g_pmin + NROWS * OUT_F)[v];
    const float4 bz = reinterpret_cast<const float4*>(bias)[v & (OUT_F / 4 - 1)];

    float4 r;
    r.x = fmaxf(ma.x, mb.x) + fminf(na.x, nb.x) + bz.x;
    r.y = fmaxf(ma.y, mb.y) + fminf(na.y, nb.y) + bz.y;
    r.z = fmaxf(ma.z, mb.z) + fminf(na.z, nb.z) + bz.z;
    r.w = fmaxf(ma.w, mb.w) + fminf(na.w, nb.w) + bz.w;
    reinterpret_cast<float4*>(out)[v] = r;
}

extern "C" void kernel_launch(void* const* d_in, const int* in_sizes, int n_in,
                              void* d_out, int out_size)
{
    const float* x    = (const float*)d_in[0];   // [2048, 512]
    const float* w    = (const float*)d_in[1];   // [256, 512]
    const float* bias = (const float*)d_in[2];   // [256]
    float* out        = (float*)d_out;           // [2048, 256]

    dim3 grid(OUT_F / TJ, NROWS / TN, NSPLIT);   // (8, 64, 2) = 1024 CTAs
    mam_partial_kernel<<<grid, THREADS>>>(x, w);

    const int total4 = NROWS * OUT_F / 4;        // 131072
    mam_combine_kernel<<<total4 / 256, 256>>>(bias, out);
}